// round 12
// baseline (speedup 1.0000x reference)
#include <cuda_runtime.h>

#define NSAMP 65536
#define EPSF 1e-8f
#define BLOCK_THREADS 128
#define NBLOCKS 740                    // 5 CTAs/SM x 148 SMs: single resident wave
#define TOTAL_WARPS (NBLOCKS * (BLOCK_THREADS / 32))

// Packed per-(o,i) params, built once per launch by prep_kernel:
//   gP[2*pi+0] = (qw,qx,qy,qz) scaled+normalized
//   gP[2*pi+1] = (t1,t2,t3,0)
__device__ float4 gP[512];

__device__ __forceinline__ float fastrcp(float d) {
    float r;
    asm("rcp.approx.f32 %0, %1;" : "=f"(r) : "f"(d));
    return r;
}

__global__ void prep_kernel(const float* __restrict__ quats,
                            const float* __restrict__ scale,
                            const float* __restrict__ trans)
{
    const int pi = threadIdx.x;            // 256 records
    const float4 q = ((const float4*)quats)[pi];
    const float f = rsqrtf(fmaf(q.x, q.x, fmaf(q.y, q.y, fmaf(q.z, q.z, q.w * q.w))) + EPSF)
                    * scale[pi];
    gP[2 * pi + 0] = make_float4(q.x * f, q.y * f, q.z * f, q.w * f);
    gP[2 * pi + 1] = make_float4(trans[3 * pi + 0], trans[3 * pi + 1], trans[3 * pi + 2], 0.0f);
}

// Warp-per-sample, single-wave persistent kernel @ 5 CTAs/SM.
// Lane l -> (o = l>>1, i-half h = l&1); lane owns pairs (o, i = h*8+k), k=0..7.
// Params are re-loaded per sample from gP (L1-hot) instead of living in
// registers -- trades ~64 L1 cycles/sample for 25% more resident warps.

__global__ void __launch_bounds__(BLOCK_THREADS, 5)
caps_quat_kernel(const float* __restrict__ x,
                 const float* __restrict__ bias,
                 const float* __restrict__ beta,
                 const float* __restrict__ alpha,
                 float* __restrict__ out)
{
    const int lane = threadIdx.x & 31;
    const int warp = blockIdx.x * (BLOCK_THREADS / 32) + (threadIdx.x >> 5);
    const int h    = lane & 1;       // i-half
    const int o    = lane >> 1;      // output capsule
    const int pbase = 2 * (o * 16 + h * 8);   // gP index of this lane's k=0 record

    const float bet = __ldg(&beta[o]);
    const float ab  = __ldg(&alpha[o]) + __ldg(&bias[o]);

    const float4* __restrict__ x4   = (const float4*)x;
    float4* __restrict__       out4 = (float4*)out;

    const bool b4  = (lane & 4)  != 0;
    const bool b8  = (lane & 8)  != 0;
    const bool b16 = (lane & 16) != 0;

#pragma unroll 1
    for (int n = warp; n < NSAMP; n += TOTAL_WARPS) {
        // Launder the param pointer so ptxas cannot hoist the loop-invariant
        // param loads out of the sample loop (that would re-pin 56 registers).
        const float4* pp = gP;
        asm volatile("" : "+l"(pp));

        // ---- votes: Hamilton product; params streamed from L1 ----
        float vw[8], vx[8], vy[8], vz[8];
#pragma unroll
        for (int k = 0; k < 8; k++) {
            const float4 X = __ldg(&x4[n * 16 + h * 8 + k]);
            const float4 Q = __ldg(&pp[pbase + 2 * k + 0]);
            const float4 T = __ldg(&pp[pbase + 2 * k + 1]);
            vw[k] = fmaf(Q.x, X.x, fmaf(-Q.y, X.y, fmaf(-Q.z, X.z, -Q.w * X.w)));
            vx[k] = fmaf(Q.x, X.y, fmaf( Q.y, X.x, fmaf( Q.z, X.w, fmaf(-Q.w, X.z, T.x))));
            vy[k] = fmaf(Q.x, X.z, fmaf(-Q.y, X.w, fmaf( Q.z, X.x, fmaf( Q.w, X.y, T.y))));
            vz[k] = fmaf(Q.x, X.w, fmaf( Q.y, X.z, fmaf(-Q.z, X.y, fmaf( Q.w, X.x, T.z))));
        }

        // ---- dynamic routing, 3 iterations ----
        float bb[8];
        float s0, s1, s2, s3, v0, v1, v2, v3, n2 = 0.0f;

#pragma unroll
        for (int iter = 0; iter < 3; iter++) {
            if (iter == 0) {
                // b == 0 -> uniform coupling c = 1/16 (tree-shaped sums)
                s0 = (((vw[0] + vw[1]) + (vw[2] + vw[3])) + ((vw[4] + vw[5]) + (vw[6] + vw[7]))) * 0.0625f;
                s1 = (((vx[0] + vx[1]) + (vx[2] + vx[3])) + ((vx[4] + vx[5]) + (vx[6] + vx[7]))) * 0.0625f;
                s2 = (((vy[0] + vy[1]) + (vy[2] + vy[3])) + ((vy[4] + vy[5]) + (vy[6] + vy[7]))) * 0.0625f;
                s3 = (((vz[0] + vz[1]) + (vz[2] + vz[3])) + ((vz[4] + vz[5]) + (vz[6] + vz[7]))) * 0.0625f;
            } else {
                // softmax over o (no max-shift; |b| bounded, f32-safe)
                float e[8], r[8];
#pragma unroll
                for (int k = 0; k < 8; k++) { e[k] = __expf(bb[k]); r[k] = e[k]; }

                // --- reduce-scatter of den over o-lanes (masks 16,8,4,2) ---
#pragma unroll
                for (int j = 0; j < 4; j++) {
                    const float snd = b16 ? r[j] : r[j + 4];
                    const float rcv = __shfl_xor_sync(0xffffffffu, snd, 16);
                    r[j] = (b16 ? r[j + 4] : r[j]) + rcv;
                }
#pragma unroll
                for (int j = 0; j < 2; j++) {
                    const float snd = b8 ? r[j] : r[j + 2];
                    const float rcv = __shfl_xor_sync(0xffffffffu, snd, 8);
                    r[j] = (b8 ? r[j + 2] : r[j]) + rcv;
                }
                {
                    const float snd = b4 ? r[0] : r[1];
                    const float rcv = __shfl_xor_sync(0xffffffffu, snd, 4);
                    r[0] = (b4 ? r[1] : r[0]) + rcv;
                }
                r[0] += __shfl_xor_sync(0xffffffffu, r[0], 2);

                const float rd = fastrcp(r[0]);

                // --- all-gather of reciprocal dens (masks 4,8,16) ---
                float g0, g1, g2, g3, rden[8];
                {
                    const float p = __shfl_xor_sync(0xffffffffu, rd, 4);
                    g0 = b4 ? p : rd;
                    g1 = b4 ? rd : p;
                }
                {
                    const float p0 = __shfl_xor_sync(0xffffffffu, g0, 8);
                    const float p1 = __shfl_xor_sync(0xffffffffu, g1, 8);
                    g2 = b8 ? g0 : p0;  g3 = b8 ? g1 : p1;
                    g0 = b8 ? p0 : g0;  g1 = b8 ? p1 : g1;
                }
                {
                    const float p0 = __shfl_xor_sync(0xffffffffu, g0, 16);
                    const float p1 = __shfl_xor_sync(0xffffffffu, g1, 16);
                    const float p2 = __shfl_xor_sync(0xffffffffu, g2, 16);
                    const float p3 = __shfl_xor_sync(0xffffffffu, g3, 16);
                    rden[0] = b16 ? p0 : g0;  rden[1] = b16 ? p1 : g1;
                    rden[2] = b16 ? p2 : g2;  rden[3] = b16 ? p3 : g3;
                    rden[4] = b16 ? g0 : p0;  rden[5] = b16 ? g1 : p1;
                    rden[6] = b16 ? g2 : p2;  rden[7] = b16 ? g3 : p3;
                }

                float c[8];
#pragma unroll
                for (int k = 0; k < 8; k++) c[k] = e[k] * rden[k];

                // weighted einsum, tree-shaped
                {
                    const float a0 = fmaf(c[1], vw[1], c[0] * vw[0]);
                    const float a1 = fmaf(c[3], vw[3], c[2] * vw[2]);
                    const float a2 = fmaf(c[5], vw[5], c[4] * vw[4]);
                    const float a3 = fmaf(c[7], vw[7], c[6] * vw[6]);
                    s0 = (a0 + a1) + (a2 + a3);
                }
                {
                    const float a0 = fmaf(c[1], vx[1], c[0] * vx[0]);
                    const float a1 = fmaf(c[3], vx[3], c[2] * vx[2]);
                    const float a2 = fmaf(c[5], vx[5], c[4] * vx[4]);
                    const float a3 = fmaf(c[7], vx[7], c[6] * vx[6]);
                    s1 = (a0 + a1) + (a2 + a3);
                }
                {
                    const float a0 = fmaf(c[1], vy[1], c[0] * vy[0]);
                    const float a1 = fmaf(c[3], vy[3], c[2] * vy[2]);
                    const float a2 = fmaf(c[5], vy[5], c[4] * vy[4]);
                    const float a3 = fmaf(c[7], vy[7], c[6] * vy[6]);
                    s2 = (a0 + a1) + (a2 + a3);
                }
                {
                    const float a0 = fmaf(c[1], vz[1], c[0] * vz[0]);
                    const float a1 = fmaf(c[3], vz[3], c[2] * vz[2]);
                    const float a2 = fmaf(c[5], vz[5], c[4] * vz[4]);
                    const float a3 = fmaf(c[7], vz[7], c[6] * vz[6]);
                    s3 = (a0 + a1) + (a2 + a3);
                }
            }
            // fold the two i-halves
            s0 += __shfl_xor_sync(0xffffffffu, s0, 1);
            s1 += __shfl_xor_sync(0xffffffffu, s1, 1);
            s2 += __shfl_xor_sync(0xffffffffu, s2, 1);
            s3 += __shfl_xor_sync(0xffffffffu, s3, 1);

            // squash factor (MUFU chain), overlapped with b-update dot products
            n2 = fmaf(s0, s0, fmaf(s1, s1, fmaf(s2, s2, s3 * s3)));
            const float fac = n2 * fastrcp(1.0f + n2) * rsqrtf(n2 + EPSF);

            if (iter == 0) {
#pragma unroll
                for (int k = 0; k < 8; k++) {
                    const float d = fmaf(s0, vw[k], fmaf(s1, vx[k], fmaf(s2, vy[k], s3 * vz[k])));
                    bb[k] = fac * d;
                }
            } else if (iter == 1) {
#pragma unroll
                for (int k = 0; k < 8; k++) {
                    const float d = fmaf(s0, vw[k], fmaf(s1, vx[k], fmaf(s2, vy[k], s3 * vz[k])));
                    bb[k] = fmaf(fac, d, bb[k]);
                }
            }

            v0 = s0 * fac; v1 = s1 * fac; v2 = s2 * fac; v3 = s3 * fac;
        }

        // ---- activation + store (even lanes: one coalesced float4 per (n,o)) ----
        const float norm_s = sqrtf(n2 + EPSF);
        const float z = fmaf(bet, norm_s, ab);
        const float a = fastrcp(1.0f + __expf(-z));

        if (h == 0) {
            out4[n * 16 + o] = make_float4(v0 * a, v1 * a, v2 * a, v3 * a);
        }
    }
}

extern "C" void kernel_launch(void* const* d_in, const int* in_sizes, int n_in,
                              void* d_out, int out_size)
{
    const float* x     = (const float*)d_in[0];
    const float* quats = (const float*)d_in[1];
    const float* scale = (const float*)d_in[2];
    const float* trans = (const float*)d_in[3];
    const float* bias  = (const float*)d_in[4];
    const float* beta  = (const float*)d_in[5];
    const float* alpha = (const float*)d_in[6];

    prep_kernel<<<1, 256>>>(quats, scale, trans);
    caps_quat_kernel<<<NBLOCKS, BLOCK_THREADS>>>(x, bias, beta, alpha, (float*)d_out);
}

// round 13
// speedup vs baseline: 4.5670x; 4.5670x over previous
#include <cuda_runtime.h>

#define NSAMP 65536
#define EPSF 1e-8f
#define BLOCK_THREADS 128
#define NBLOCKS 592                    // 4 CTAs/SM x 148 SMs: single resident wave
#define TOTAL_WARPS (NBLOCKS * (BLOCK_THREADS / 32))

// Warp-per-sample, register-resident, single-wave persistent kernel.
// Lane l -> (o = l>>1, i-half h = l&1).
// BUTTERFLY SLOT ORDER: slot m holds logical i = h*8 + (m ^ perm), with
// perm = bit0:lane&4, bit1:lane&8, bit2:lane&16. This makes the softmax-den
// reduce-scatter/all-gather completely select-free (pure shfl+add), since
// partners at mask 16/8/4 differ exactly in perm bit 2/1/0.
// All other per-k uses (sums, exp, b-update) are k-symmetric -> unaffected.

__device__ __forceinline__ float fastrcp(float d) {
    float r;
    asm("rcp.approx.f32 %0, %1;" : "=f"(r) : "f"(d));
    return r;
}

__global__ void __launch_bounds__(BLOCK_THREADS, 4)
caps_quat_kernel(const float* __restrict__ x,
                 const float* __restrict__ quats,
                 const float* __restrict__ scale,
                 const float* __restrict__ trans,
                 const float* __restrict__ bias,
                 const float* __restrict__ beta,
                 const float* __restrict__ alpha,
                 float* __restrict__ out)
{
    const int lane = threadIdx.x & 31;
    const int warp = blockIdx.x * (BLOCK_THREADS / 32) + (threadIdx.x >> 5);
    const int h    = lane & 1;       // i-half
    const int o    = lane >> 1;      // output capsule

    // butterfly permutation of this lane's 8 slots
    const int perm = ((lane >> 2) & 1) | ((lane >> 2) & 2) | ((lane >> 2) & 4);

    // ---- one-time prologue: scaled quaternion + trans, loaded in slot order ----
    float qw[8], qx[8], qy[8], qz[8], t1[8], t2[8], t3[8];
    const float4* __restrict__ q4 = (const float4*)quats;
#pragma unroll
    for (int m = 0; m < 8; m++) {
        const int pi = o * 16 + h * 8 + (m ^ perm);
        const float4 q = __ldg(&q4[pi]);
        const float f = rsqrtf(fmaf(q.x, q.x, fmaf(q.y, q.y, fmaf(q.z, q.z, q.w * q.w))) + EPSF)
                        * __ldg(&scale[pi]);
        qw[m] = q.x * f; qx[m] = q.y * f; qy[m] = q.z * f; qz[m] = q.w * f;
        t1[m] = __ldg(&trans[pi * 3 + 0]);
        t2[m] = __ldg(&trans[pi * 3 + 1]);
        t3[m] = __ldg(&trans[pi * 3 + 2]);
    }
    const float bet = __ldg(&beta[o]);
    const float ab  = __ldg(&alpha[o]) + __ldg(&bias[o]);

    const float4* __restrict__ x4   = (const float4*)x;
    float4* __restrict__       out4 = (float4*)out;

#pragma unroll 1
    for (int n = warp; n < NSAMP; n += TOTAL_WARPS) {
        // ---- votes: Hamilton product (x loaded in slot order) ----
        float vw[8], vx[8], vy[8], vz[8];
#pragma unroll
        for (int m = 0; m < 8; m++) {
            const float4 X = __ldg(&x4[n * 16 + h * 8 + (m ^ perm)]);
            vw[m] = fmaf(qw[m], X.x, fmaf(-qx[m], X.y, fmaf(-qy[m], X.z, -qz[m] * X.w)));
            vx[m] = fmaf(qw[m], X.y, fmaf( qx[m], X.x, fmaf( qy[m], X.w, fmaf(-qz[m], X.z, t1[m]))));
            vy[m] = fmaf(qw[m], X.z, fmaf(-qx[m], X.w, fmaf( qy[m], X.x, fmaf( qz[m], X.y, t2[m]))));
            vz[m] = fmaf(qw[m], X.w, fmaf( qx[m], X.z, fmaf(-qy[m], X.y, fmaf( qz[m], X.x, t3[m]))));
        }

        // prefetch next sample's x into L1 (16 lanes cover the 256B sample)
        {
            const int nn = n + TOTAL_WARPS;
            if (nn < NSAMP) {
                const char* pa = (const char*)(x4 + nn * 16) + (lane & 15) * 16;
                asm volatile("prefetch.global.L1 [%0];" :: "l"(pa));
            }
        }

        // ---- dynamic routing, 3 iterations ----
        float bb[8];
        float s0, s1, s2, s3, v0, v1, v2, v3, n2 = 0.0f;

#pragma unroll
        for (int iter = 0; iter < 3; iter++) {
            if (iter == 0) {
                // b == 0 -> uniform coupling c = 1/16 (tree-shaped sums)
                s0 = (((vw[0] + vw[1]) + (vw[2] + vw[3])) + ((vw[4] + vw[5]) + (vw[6] + vw[7]))) * 0.0625f;
                s1 = (((vx[0] + vx[1]) + (vx[2] + vx[3])) + ((vx[4] + vx[5]) + (vx[6] + vx[7]))) * 0.0625f;
                s2 = (((vy[0] + vy[1]) + (vy[2] + vy[3])) + ((vy[4] + vy[5]) + (vy[6] + vy[7]))) * 0.0625f;
                s3 = (((vz[0] + vz[1]) + (vz[2] + vz[3])) + ((vz[4] + vz[5]) + (vz[6] + vz[7]))) * 0.0625f;
            } else {
                // softmax over o (no max-shift; |b| bounded, f32-safe)
                float e[8], r[8];
#pragma unroll
                for (int m = 0; m < 8; m++) { e[m] = __expf(bb[m]); r[m] = e[m]; }

                // --- select-free reduce-scatter (invariant: slot m <-> logical m^perm) ---
#pragma unroll
                for (int j = 0; j < 4; j++)
                    r[j] += __shfl_xor_sync(0xffffffffu, r[j + 4], 16);
#pragma unroll
                for (int j = 0; j < 2; j++)
                    r[j] += __shfl_xor_sync(0xffffffffu, r[j + 2], 8);
                r[0] += __shfl_xor_sync(0xffffffffu, r[1], 4);
                r[0] += __shfl_xor_sync(0xffffffffu, r[0], 2);

                // one reciprocal per lane: rden for logical k = perm (slot 0)
                float rden[8];
                rden[0] = fastrcp(r[0]);

                // --- select-free all-gather ---
                rden[1] = __shfl_xor_sync(0xffffffffu, rden[0], 4);
                rden[2] = __shfl_xor_sync(0xffffffffu, rden[0], 8);
                rden[3] = __shfl_xor_sync(0xffffffffu, rden[1], 8);
                rden[4] = __shfl_xor_sync(0xffffffffu, rden[0], 16);
                rden[5] = __shfl_xor_sync(0xffffffffu, rden[1], 16);
                rden[6] = __shfl_xor_sync(0xffffffffu, rden[2], 16);
                rden[7] = __shfl_xor_sync(0xffffffffu, rden[3], 16);

                float c[8];
#pragma unroll
                for (int m = 0; m < 8; m++) c[m] = e[m] * rden[m];

                // weighted einsum, tree-shaped
                {
                    const float a0 = fmaf(c[1], vw[1], c[0] * vw[0]);
                    const float a1 = fmaf(c[3], vw[3], c[2] * vw[2]);
                    const float a2 = fmaf(c[5], vw[5], c[4] * vw[4]);
                    const float a3 = fmaf(c[7], vw[7], c[6] * vw[6]);
                    s0 = (a0 + a1) + (a2 + a3);
                }
                {
                    const float a0 = fmaf(c[1], vx[1], c[0] * vx[0]);
                    const float a1 = fmaf(c[3], vx[3], c[2] * vx[2]);
                    const float a2 = fmaf(c[5], vx[5], c[4] * vx[4]);
                    const float a3 = fmaf(c[7], vx[7], c[6] * vx[6]);
                    s1 = (a0 + a1) + (a2 + a3);
                }
                {
                    const float a0 = fmaf(c[1], vy[1], c[0] * vy[0]);
                    const float a1 = fmaf(c[3], vy[3], c[2] * vy[2]);
                    const float a2 = fmaf(c[5], vy[5], c[4] * vy[4]);
                    const float a3 = fmaf(c[7], vy[7], c[6] * vy[6]);
                    s2 = (a0 + a1) + (a2 + a3);
                }
                {
                    const float a0 = fmaf(c[1], vz[1], c[0] * vz[0]);
                    const float a1 = fmaf(c[3], vz[3], c[2] * vz[2]);
                    const float a2 = fmaf(c[5], vz[5], c[4] * vz[4]);
                    const float a3 = fmaf(c[7], vz[7], c[6] * vz[6]);
                    s3 = (a0 + a1) + (a2 + a3);
                }
            }
            // fold the two i-halves
            s0 += __shfl_xor_sync(0xffffffffu, s0, 1);
            s1 += __shfl_xor_sync(0xffffffffu, s1, 1);
            s2 += __shfl_xor_sync(0xffffffffu, s2, 1);
            s3 += __shfl_xor_sync(0xffffffffu, s3, 1);

            // squash factor (MUFU chain), overlapped with b-update dot products
            n2 = fmaf(s0, s0, fmaf(s1, s1, fmaf(s2, s2, s3 * s3)));
            const float fac = n2 * fastrcp(1.0f + n2) * rsqrtf(n2 + EPSF);

            if (iter == 0) {
#pragma unroll
                for (int m = 0; m < 8; m++) {
                    const float d = fmaf(s0, vw[m], fmaf(s1, vx[m], fmaf(s2, vy[m], s3 * vz[m])));
                    bb[m] = fac * d;
                }
            } else if (iter == 1) {
#pragma unroll
                for (int m = 0; m < 8; m++) {
                    const float d = fmaf(s0, vw[m], fmaf(s1, vx[m], fmaf(s2, vy[m], s3 * vz[m])));
                    bb[m] = fmaf(fac, d, bb[m]);
                }
            }

            v0 = s0 * fac; v1 = s1 * fac; v2 = s2 * fac; v3 = s3 * fac;
        }

        // ---- activation + store (even lanes: one coalesced float4 per (n,o)) ----
        const float norm_s = sqrtf(n2 + EPSF);
        const float z = fmaf(bet, norm_s, ab);
        const float a = fastrcp(1.0f + __expf(-z));

        if (h == 0) {
            out4[n * 16 + o] = make_float4(v0 * a, v1 * a, v2 * a, v3 * a);
        }
    }
}

extern "C" void kernel_launch(void* const* d_in, const int* in_sizes, int n_in,
                              void* d_out, int out_size)
{
    const float* x     = (const float*)d_in[0];
    const float* quats = (const float*)d_in[1];
    const float* scale = (const float*)d_in[2];
    const float* trans = (const float*)d_in[3];
    const float* bias  = (const float*)d_in[4];
    const float* beta  = (const float*)d_in[5];
    const float* alpha = (const float*)d_in[6];

    caps_quat_kernel<<<NBLOCKS, BLOCK_THREADS>>>(x, quats, scale, trans, bias, beta, alpha,
                                                 (float*)d_out);
}